// round 12
// baseline (speedup 1.0000x reference)
#include <cuda_runtime.h>
#include <cuda_bf16.h>
#include <math.h>
#include <stdint.h>

#define NN 100000
#define EE 600000
#define DIN 256
#define DH  128
#define DE  64
#define NB  ((NN + 1023) / 1024)

// weight pack offsets (u32 packs, [k2][M] layout per segment)
#define OFF_W1  0        // Kp=128, M=128
#define OFF_W2  16384    // Kp=64,  M=128
#define OFF_W3  24576    // Kp=64,  M=64
#define OFF_WD1 28672    // Kp=32,  M=128
#define OFF_WD2 32768    // Kp=64,  M=256
#define WPACKS  49152

// ---------------- scratch (static device globals; no allocation) ------------
__device__ float    g_h  [(size_t)NN * DH];   // GEMM f32 output (pre-agg)
__device__ uint32_t g_ah [(size_t)NN * 128];  // activation split hi (bf16x2 packs)
__device__ uint32_t g_al [(size_t)NN * 128];  // activation split lo
__device__ uint32_t g_zh [(size_t)NN * 32];   // z split hi
__device__ uint32_t g_zl [(size_t)NN * 32];   // z split lo
__device__ uint32_t g_wbh[WPACKS];            // weight split hi
__device__ uint32_t g_wbl[WPACKS];            // weight split lo
__device__ float    g_din[NN];
__device__ int      g_cnt[NN];
__device__ int      g_rowptr[NN + 1];
__device__ int      g_cur[NN];
__device__ int      g_bsum[NB];
__device__ int      g_ssrc [EE];
__device__ float    g_scoef[EE];
__device__ int      g_src[EE];
__device__ int      g_dst[EE];
__device__ int      g_is64;

// split f0,f1 -> packed bf16x2 hi / lo
__device__ __forceinline__ void splitbf2(float f0, float f1, uint32_t& hi, uint32_t& lo) {
    __nv_bfloat162 h = __floats2bfloat162_rn(f0, f1);
    float r0 = f0 - __bfloat162float(h.x);
    float r1 = f1 - __bfloat162float(h.y);
    __nv_bfloat162 l = __floats2bfloat162_rn(r0, r1);
    hi = *reinterpret_cast<uint32_t*>(&h);
    lo = *reinterpret_cast<uint32_t*>(&l);
}

// ---------------- edge-index dtype detection + conversion -------------------
__global__ void detect_kernel(const int* __restrict__ w) {
    if (threadIdx.x == 0 && blockIdx.x == 0) {
        int is64 = 1;
        for (int i = 1; i < 128; i += 2)
            if (w[i] != 0) { is64 = 0; break; }
        g_is64 = is64;
    }
}

__global__ void convert_kernel(const void* __restrict__ ei) {
    int e = blockIdx.x * blockDim.x + threadIdx.x;
    if (e >= 2 * EE) return;
    int v;
    if (g_is64) v = (int)((const long long*)ei)[e];
    else        v = ((const int*)ei)[e];
    v = max(0, min(NN - 1, v));
    if (e < EE) g_src[e] = v;
    else        { g_dst[e - EE] = v; atomicAdd(&g_cnt[v], 1); }
}

__global__ void zero_cnt_kernel() {
    int i = blockIdx.x * blockDim.x + threadIdx.x;
    if (i < NN) g_cnt[i] = 0;
}

__global__ void scan1_kernel() {
    __shared__ int s[1024];
    int i = blockIdx.x * 1024 + threadIdx.x;
    int v = (i < NN) ? g_cnt[i] : 0;
    if (i < NN) g_din[i] = rsqrtf((float)v + 1.0f);
    s[threadIdx.x] = v;
    __syncthreads();
    for (int off = 1; off < 1024; off <<= 1) {
        int t = (threadIdx.x >= off) ? s[threadIdx.x - off] : 0;
        __syncthreads();
        s[threadIdx.x] += t;
        __syncthreads();
    }
    if (i < NN) g_rowptr[i + 1] = s[threadIdx.x];
    if (threadIdx.x == 1023) g_bsum[blockIdx.x] = s[1023];
}

__global__ void scan2_kernel() {
    if (threadIdx.x == 0 && blockIdx.x == 0) {
        int run = 0;
        for (int b = 0; b < NB; b++) { int t = g_bsum[b]; g_bsum[b] = run; run += t; }
        g_rowptr[0] = 0;
    }
}

__global__ void scan3_kernel() {
    int i = blockIdx.x * blockDim.x + threadIdx.x;
    if (i < NN) {
        int v = g_rowptr[i + 1] + g_bsum[i >> 10];
        g_rowptr[i + 1] = v;
        g_cur[i] = v - g_cnt[i];
    }
}

__global__ void fill_csr_kernel() {
    int e = blockIdx.x * blockDim.x + threadIdx.x;
    if (e >= EE) return;
    int s = g_src[e];
    int d = g_dst[e];
    int slot = atomicAdd(&g_cur[d], 1);
    g_ssrc[slot]  = s;
    g_scoef[slot] = g_din[s] * g_din[d];
}

// ---------------- pre-split kernels -------------------------------------------
// all 5 weight matrices -> packed [k2][M] hi/lo
__global__ void wsplit_kernel(const float* __restrict__ W1, const float* __restrict__ W2,
                              const float* __restrict__ W3, const float* __restrict__ Wd1,
                              const float* __restrict__ Wd2) {
    int idx = blockIdx.x * blockDim.x + threadIdx.x;
    if (idx >= WPACKS) return;
    const float* W; int M, off;
    if      (idx < OFF_W2)  { W = W1;  M = 128; off = OFF_W1; }
    else if (idx < OFF_W3)  { W = W2;  M = 128; off = OFF_W2; }
    else if (idx < OFF_WD1) { W = W3;  M = 64;  off = OFF_W3; }
    else if (idx < OFF_WD2) { W = Wd1; M = 128; off = OFF_WD1; }
    else                    { W = Wd2; M = 256; off = OFF_WD2; }
    int local = idx - off;
    int k2 = local / M, m = local - k2 * M;
    uint32_t h, l;
    splitbf2(W[(2 * k2) * M + m], W[(2 * k2 + 1) * M + m], h, l);
    g_wbh[idx] = h;
    g_wbl[idx] = l;
}

// x [NN,256] f32 -> g_ah/g_al packed (128 packs/row)
__global__ void xsplit_kernel(const float* __restrict__ x) {
    size_t idx = (size_t)blockIdx.x * blockDim.x + threadIdx.x;
    if (idx >= (size_t)NN * 128) return;
    float2 v = *reinterpret_cast<const float2*>(x + idx * 2);
    uint32_t h, l;
    splitbf2(v.x, v.y, h, l);
    g_ah[idx] = h;
    g_al[idx] = l;
}

// ---------------- fused aggregation (gather + self-loop + bias + relu + split)
__global__ void agg_d128_kernel(const float* __restrict__ bias) {
    int warp = (blockIdx.x * blockDim.x + threadIdx.x) >> 5;
    int lane = threadIdx.x & 31;
    if (warp >= NN) return;
    int rs = g_rowptr[warp], re = g_rowptr[warp + 1];
    float di = g_din[warp];
    float sc = di * di;
    float4 acc = *reinterpret_cast<const float4*>(g_h + (size_t)warp * 128 + lane * 4);
    acc.x *= sc; acc.y *= sc; acc.z *= sc; acc.w *= sc;
    for (int j = rs; j < re; j++) {
        int s = g_ssrc[j];
        float c = g_scoef[j];
        float4 v = *reinterpret_cast<const float4*>(g_h + (size_t)s * 128 + lane * 4);
        acc.x += v.x * c; acc.y += v.y * c; acc.z += v.z * c; acc.w += v.w * c;
    }
    float4 b = *reinterpret_cast<const float4*>(bias + lane * 4);
    acc.x = fmaxf(acc.x + b.x, 0.0f);
    acc.y = fmaxf(acc.y + b.y, 0.0f);
    acc.z = fmaxf(acc.z + b.z, 0.0f);
    acc.w = fmaxf(acc.w + b.w, 0.0f);
    uint32_t h0, l0, h1, l1;
    splitbf2(acc.x, acc.y, h0, l0);
    splitbf2(acc.z, acc.w, h1, l1);
    size_t o = (size_t)warp * 64 + lane * 2;
    g_ah[o] = h0; g_ah[o + 1] = h1;
    g_al[o] = l0; g_al[o + 1] = l1;
}

// layer3: f32 z to output AND split into g_zh/g_zl
__global__ void agg_d64_kernel(const float* __restrict__ bias, float* __restrict__ zout) {
    int warp = (blockIdx.x * blockDim.x + threadIdx.x) >> 5;
    int lane = threadIdx.x & 31;
    if (warp >= NN) return;
    int rs = g_rowptr[warp], re = g_rowptr[warp + 1];
    float di = g_din[warp];
    float sc = di * di;
    float2 acc = *reinterpret_cast<const float2*>(g_h + (size_t)warp * 64 + lane * 2);
    acc.x *= sc; acc.y *= sc;
    for (int j = rs; j < re; j++) {
        int s = g_ssrc[j];
        float c = g_scoef[j];
        float2 v = *reinterpret_cast<const float2*>(g_h + (size_t)s * 64 + lane * 2);
        acc.x += v.x * c; acc.y += v.y * c;
    }
    float2 b = *reinterpret_cast<const float2*>(bias + lane * 2);
    acc.x += b.x; acc.y += b.y;
    *reinterpret_cast<float2*>(zout + (size_t)warp * 64 + lane * 2) = acc;
    uint32_t h, l;
    splitbf2(acc.x, acc.y, h, l);
    g_zh[(size_t)warp * 32 + lane] = h;
    g_zl[(size_t)warp * 32 + lane] = l;
}

// ---------------- BF16x3 tensor-core GEMM (pre-split inputs) -----------------
// C[N,M] = A[N,K] @ W[K,M]; A from g_ah/g_al (or g_zh/g_zl), W from g_wbh/g_wbl.
// block tile 128x64, 8 warps, warp tile 32x32; GBK=32 k (16 packs) per stage.
// Inner loop: pure LDS + mma (no conversions).
#define GBM 128
#define GBN 64
#define KPT 16    // packs per chunk
#define APAD 4    // A stride 20 u32: frag banks all distinct
#define BPAD 8    // B stride 72 u32: frag banks all distinct

__device__ __forceinline__ void mma_bf16(float c[4],
                                         uint32_t a0, uint32_t a1, uint32_t a2, uint32_t a3,
                                         uint32_t b0, uint32_t b1) {
    asm("mma.sync.aligned.m16n8k16.row.col.f32.bf16.bf16.f32 "
        "{%0,%1,%2,%3}, {%4,%5,%6,%7}, {%8,%9}, {%0,%1,%2,%3};"
        : "+f"(c[0]), "+f"(c[1]), "+f"(c[2]), "+f"(c[3])
        : "r"(a0), "r"(a1), "r"(a2), "r"(a3), "r"(b0), "r"(b1));
}

__global__ void __launch_bounds__(256, 2)
gemm_tc_kernel(int a_sel, int Kp, int wt_off,
               const float* __restrict__ bias,
               float* C_ext, int write_split,
               int M, int do_relu) {
    __shared__ uint32_t AsH[GBM][KPT + APAD];
    __shared__ uint32_t AsL[GBM][KPT + APAD];
    __shared__ uint32_t BsH[KPT][GBN + BPAD];
    __shared__ uint32_t BsL[KPT][GBN + BPAD];

    const uint32_t* Ah = a_sel ? g_zh : g_ah;
    const uint32_t* Al = a_sel ? g_zl : g_al;
    const uint32_t* WH = g_wbh + wt_off;
    const uint32_t* WL = g_wbl + wt_off;
    float* C = C_ext ? C_ext : g_h;

    int tid  = threadIdx.x;
    int wid  = tid >> 5;
    int lane = tid & 31;
    int wm   = wid & 3;
    int wn   = wid >> 2;
    int group = lane >> 2;
    int tig   = lane & 3;

    int row0 = blockIdx.y * GBM;
    int col0 = blockIdx.x * GBN;

    float acc[2][4][4];
#pragma unroll
    for (int mi = 0; mi < 2; mi++)
#pragma unroll
        for (int ni = 0; ni < 4; ni++)
#pragma unroll
            for (int q = 0; q < 4; q++) acc[mi][ni][q] = 0.0f;

    uint4 pah[2], pal[2], pbh, pbl;

    auto loadTile = [&](int k0p) {
#pragma unroll
        for (int q = 0; q < 2; q++) {
            int f4 = tid * 2 + q;          // 0..511
            int r  = f4 >> 2;
            int c4 = (f4 & 3) * 4;
            int gr = row0 + r;
            if (gr < NN) {
                pah[q] = *reinterpret_cast<const uint4*>(Ah + (size_t)gr * Kp + k0p + c4);
                pal[q] = *reinterpret_cast<const uint4*>(Al + (size_t)gr * Kp + k0p + c4);
            } else {
                pah[q] = make_uint4(0, 0, 0, 0);
                pal[q] = make_uint4(0, 0, 0, 0);
            }
        }
        {
            int k2 = tid >> 4;             // 0..15
            int n4 = (tid & 15) * 4;
            pbh = *reinterpret_cast<const uint4*>(WH + (size_t)(k0p + k2) * M + col0 + n4);
            pbl = *reinterpret_cast<const uint4*>(WL + (size_t)(k0p + k2) * M + col0 + n4);
        }
    };

    auto storeTile = [&]() {
#pragma unroll
        for (int q = 0; q < 2; q++) {
            int f4 = tid * 2 + q;
            int r  = f4 >> 2;
            int c4 = (f4 & 3) * 4;
            *reinterpret_cast<uint4*>(&AsH[r][c4]) = pah[q];
            *reinterpret_cast<uint4*>(&AsL[r][c4]) = pal[q];
        }
        {
            int k2 = tid >> 4;
            int n4 = (tid & 15) * 4;
            *reinterpret_cast<uint4*>(&BsH[k2][n4]) = pbh;
            *reinterpret_cast<uint4*>(&BsL[k2][n4]) = pbl;
        }
    };

    auto compute = [&]() {
#pragma unroll
        for (int ks = 0; ks < 2; ks++) {
            int kb = ks * 8;
            uint32_t ahi[2][4], alo[2][4];
            uint32_t bhi[4][2], blo[4][2];
#pragma unroll
            for (int mi = 0; mi < 2; mi++) {
                int m = wm * 32 + mi * 16 + group;
                ahi[mi][0] = AsH[m    ][kb + tig];
                ahi[mi][1] = AsH[m + 8][kb + tig];
                ahi[mi][2] = AsH[m    ][kb + tig + 4];
                ahi[mi][3] = AsH[m + 8][kb + tig + 4];
                alo[mi][0] = AsL[m    ][kb + tig];
                alo[mi][1] = AsL[m + 8][kb + tig];
                alo[mi][2] = AsL[m    ][kb + tig + 4];
                alo[mi][3] = AsL[m + 8][kb + tig + 4];
            }
#pragma unroll
            for (int ni = 0; ni < 4; ni++) {
                int n = wn * 32 + ni * 8 + group;
                bhi[ni][0] = BsH[kb + tig    ][n];
                bhi[ni][1] = BsH[kb + tig + 4][n];
                blo[ni][0] = BsL[kb + tig    ][n];
                blo[ni][1] = BsL[kb + tig + 4][n];
            }
#pragma unroll
            for (int ni = 0; ni < 4; ni++)
#pragma unroll
                for (int mi = 0; mi < 2; mi++)
                    mma_bf16(acc[mi][ni], ahi[mi][0], ahi[mi][1], ahi[mi][2], ahi[mi][3],
                             bhi[ni][0], bhi[ni][1]);
#pragma unroll
            for (int ni = 0; ni < 4; ni++)
#pragma unroll
                for (int mi = 0; mi < 2; mi++)
                    mma_bf16(acc[mi][ni], ahi[mi][0], ahi[mi][1], ahi[mi][2], ahi[mi][3],
                             blo[ni][0], blo[ni][1]);
#pragma unroll
            for (int ni = 0; ni < 4; ni++)
#pragma unroll
                for (int mi = 0; mi < 2; mi++)
                    mma_bf16(acc[mi][ni], alo[mi][0], alo[mi][1], alo[mi][2], alo[mi][3],
                             bhi[ni][0], bhi[ni][1]);
        }
    };

    loadTile(0);
    storeTile();
    __syncthreads();

    for (int k0p = KPT; k0p < Kp; k0p += KPT) {
        loadTile(k0p);
        compute();
        __syncthreads();
        storeTile();
        __syncthreads();
    }
    compute();

    // ---- epilogue ----
#pragma unroll
    for (int mi = 0; mi < 2; mi++) {
#pragma unroll
        for (int ni = 0; ni < 4; ni++) {
            int colb = col0 + wn * 32 + ni * 8 + tig * 2;
            float b0 = 0.f, b1 = 0.f;
            if (bias) { b0 = bias[colb]; b1 = bias[colb + 1]; }
#pragma unroll
            for (int half = 0; half < 2; half++) {
                int r = row0 + wm * 32 + mi * 16 + group + half * 8;
                if (r >= NN) continue;
                float v0 = acc[mi][ni][half * 2 + 0] + b0;
                float v1 = acc[mi][ni][half * 2 + 1] + b1;
                if (do_relu) { v0 = fmaxf(v0, 0.f); v1 = fmaxf(v1, 0.f); }
                if (write_split) {
                    uint32_t h, l;
                    splitbf2(v0, v1, h, l);
                    size_t o = (size_t)r * (M >> 1) + (colb >> 1);
                    g_ah[o] = h;
                    g_al[o] = l;
                } else {
                    *reinterpret_cast<float2*>(C + (size_t)r * M + colb) = make_float2(v0, v1);
                }
            }
        }
    }
}

// ---------------- orchestration ----------------------------------------------
static inline void run_gemm(int a_sel, int Kp, int wt_off, const float* bias,
                            float* C_ext, int write_split, int M, int relu) {
    dim3 grid(M / GBN, (NN + GBM - 1) / GBM);
    gemm_tc_kernel<<<grid, 256>>>(a_sel, Kp, wt_off, bias, C_ext, write_split, M, relu);
}

extern "C" void kernel_launch(void* const* d_in, const int* in_sizes, int n_in,
                              void* d_out, int out_size) {
    const float* x   = (const float*)d_in[0];
    const void*  ei  = d_in[1];
    const float* W1  = (const float*)d_in[2];
    const float* b1  = (const float*)d_in[3];
    const float* W2  = (const float*)d_in[4];
    const float* b2  = (const float*)d_in[5];
    const float* W3  = (const float*)d_in[6];
    const float* b3  = (const float*)d_in[7];
    const float* Wd1 = (const float*)d_in[8];
    const float* bd1 = (const float*)d_in[9];
    const float* Wd2 = (const float*)d_in[10];
    const float* bd2 = (const float*)d_in[11];

    float* z    = (float*)d_out;                     // [N, 64]
    float* xhat = (float*)d_out + (size_t)NN * DE;   // [N, 256]

    // ---- graph preprocessing + pre-splitting ----------------------------
    detect_kernel<<<1, 32>>>((const int*)ei);
    zero_cnt_kernel<<<(NN + 255) / 256, 256>>>();
    convert_kernel<<<(2 * EE + 255) / 256, 256>>>(ei);
    scan1_kernel<<<NB, 1024>>>();
    scan2_kernel<<<1, 32>>>();
    scan3_kernel<<<(NN + 255) / 256, 256>>>();
    fill_csr_kernel<<<(EE + 255) / 256, 256>>>();
    wsplit_kernel<<<(WPACKS + 255) / 256, 256>>>(W1, W2, W3, Wd1, Wd2);
    xsplit_kernel<<<(int)(((size_t)NN * 128 + 255) / 256), 256>>>(x);

    int aggBlocks = (NN + 7) / 8;

    // ---- layer 1: h1 = relu(gcn(x, W1, b1)) -----------------------------
    run_gemm(0, 128, OFF_W1, nullptr, nullptr, 0, DH, 0);   // g_h = x@W1
    agg_d128_kernel<<<aggBlocks, 256>>>(b1);                // -> split in g_ah/g_al

    // ---- layer 2: h2 = relu(gcn(h1, W2, b2)) ----------------------------
    run_gemm(0, 64, OFF_W2, nullptr, nullptr, 0, DH, 0);
    agg_d128_kernel<<<aggBlocks, 256>>>(b2);

    // ---- layer 3: z = gcn(h2, W3, b3) -----------------------------------
    run_gemm(0, 64, OFF_W3, nullptr, nullptr, 0, DE, 0);
    agg_d64_kernel<<<aggBlocks, 256>>>(b3, z);              // z f32 + split in g_zh/zl

    // ---- decoder: x_hat = relu(z@Wd1+bd1)@Wd2 + bd2 ---------------------
    run_gemm(1, 32, OFF_WD1, bd1, nullptr, 1, DH, 1);       // split h -> g_ah/g_al
    run_gemm(0, 64, OFF_WD2, bd2, xhat, 0, DIN, 0);
}

// round 13
// speedup vs baseline: 1.3173x; 1.3173x over previous
#include <cuda_runtime.h>
#include <cuda_bf16.h>
#include <math.h>
#include <stdint.h>

#define NN 100000
#define EE 600000
#define DIN 256
#define DH  128
#define DE  64
#define NB  ((NN + 1023) / 1024)

// weight pack offsets (u32 packs, [k2][M] layout per segment)
#define OFF_W1  0        // Kp=128, M=128
#define OFF_W2  16384    // Kp=64,  M=128
#define OFF_W3  24576    // Kp=64,  M=64
#define OFF_WD1 28672    // Kp=32,  M=128
#define OFF_WD2 32768    // Kp=64,  M=256
#define WPACKS  49152

// ---------------- scratch (static device globals; no allocation) ------------
__device__ float    g_h  [(size_t)NN * DH];   // GEMM f32 output (pre-agg)
__device__ uint32_t g_ah [(size_t)NN * 128];  // activation split hi (bf16x2 packs)
__device__ uint32_t g_al [(size_t)NN * 128];  // activation split lo
__device__ uint32_t g_zh [(size_t)NN * 32];   // z split hi
__device__ uint32_t g_zl [(size_t)NN * 32];   // z split lo
__device__ uint32_t g_wbh[WPACKS];            // weight split hi
__device__ uint32_t g_wbl[WPACKS];            // weight split lo
__device__ float    g_din[NN];
__device__ int      g_cnt[NN];
__device__ int      g_rowptr[NN + 1];
__device__ int      g_cur[NN];
__device__ int      g_bsum[NB];
__device__ int      g_ssrc [EE];
__device__ float    g_scoef[EE];
__device__ int      g_src[EE];
__device__ int      g_dst[EE];
__device__ int      g_is64;

// split f0,f1 -> packed bf16x2 hi / lo
__device__ __forceinline__ void splitbf2(float f0, float f1, uint32_t& hi, uint32_t& lo) {
    __nv_bfloat162 h = __floats2bfloat162_rn(f0, f1);
    float r0 = f0 - __bfloat162float(h.x);
    float r1 = f1 - __bfloat162float(h.y);
    __nv_bfloat162 l = __floats2bfloat162_rn(r0, r1);
    hi = *reinterpret_cast<uint32_t*>(&h);
    lo = *reinterpret_cast<uint32_t*>(&l);
}

// ---------------- edge-index dtype detection + conversion -------------------
__global__ void detect_kernel(const int* __restrict__ w) {
    if (threadIdx.x == 0 && blockIdx.x == 0) {
        int is64 = 1;
        for (int i = 1; i < 128; i += 2)
            if (w[i] != 0) { is64 = 0; break; }
        g_is64 = is64;
    }
}

__global__ void convert_kernel(const void* __restrict__ ei) {
    int e = blockIdx.x * blockDim.x + threadIdx.x;
    if (e >= 2 * EE) return;
    int v;
    if (g_is64) v = (int)((const long long*)ei)[e];
    else        v = ((const int*)ei)[e];
    v = max(0, min(NN - 1, v));
    if (e < EE) g_src[e] = v;
    else        { g_dst[e - EE] = v; atomicAdd(&g_cnt[v], 1); }
}

__global__ void zero_cnt_kernel() {
    int i = blockIdx.x * blockDim.x + threadIdx.x;
    if (i < NN) g_cnt[i] = 0;
}

__global__ void scan1_kernel() {
    __shared__ int s[1024];
    int i = blockIdx.x * 1024 + threadIdx.x;
    int v = (i < NN) ? g_cnt[i] : 0;
    if (i < NN) g_din[i] = rsqrtf((float)v + 1.0f);
    s[threadIdx.x] = v;
    __syncthreads();
    for (int off = 1; off < 1024; off <<= 1) {
        int t = (threadIdx.x >= off) ? s[threadIdx.x - off] : 0;
        __syncthreads();
        s[threadIdx.x] += t;
        __syncthreads();
    }
    if (i < NN) g_rowptr[i + 1] = s[threadIdx.x];
    if (threadIdx.x == 1023) g_bsum[blockIdx.x] = s[1023];
}

__global__ void scan2_kernel() {
    if (threadIdx.x == 0 && blockIdx.x == 0) {
        int run = 0;
        for (int b = 0; b < NB; b++) { int t = g_bsum[b]; g_bsum[b] = run; run += t; }
        g_rowptr[0] = 0;
    }
}

__global__ void scan3_kernel() {
    int i = blockIdx.x * blockDim.x + threadIdx.x;
    if (i < NN) {
        int v = g_rowptr[i + 1] + g_bsum[i >> 10];
        g_rowptr[i + 1] = v;
        g_cur[i] = v - g_cnt[i];
    }
}

__global__ void fill_csr_kernel() {
    int e = blockIdx.x * blockDim.x + threadIdx.x;
    if (e >= EE) return;
    int s = g_src[e];
    int d = g_dst[e];
    int slot = atomicAdd(&g_cur[d], 1);
    g_ssrc[slot]  = s;
    g_scoef[slot] = g_din[s] * g_din[d];
}

// ---------------- pre-split kernels -------------------------------------------
__global__ void wsplit_kernel(const float* __restrict__ W1, const float* __restrict__ W2,
                              const float* __restrict__ W3, const float* __restrict__ Wd1,
                              const float* __restrict__ Wd2) {
    int idx = blockIdx.x * blockDim.x + threadIdx.x;
    if (idx >= WPACKS) return;
    const float* W; int M, off;
    if      (idx < OFF_W2)  { W = W1;  M = 128; off = OFF_W1; }
    else if (idx < OFF_W3)  { W = W2;  M = 128; off = OFF_W2; }
    else if (idx < OFF_WD1) { W = W3;  M = 64;  off = OFF_W3; }
    else if (idx < OFF_WD2) { W = Wd1; M = 128; off = OFF_WD1; }
    else                    { W = Wd2; M = 256; off = OFF_WD2; }
    int local = idx - off;
    int k2 = local / M, m = local - k2 * M;
    uint32_t h, l;
    splitbf2(W[(2 * k2) * M + m], W[(2 * k2 + 1) * M + m], h, l);
    g_wbh[idx] = h;
    g_wbl[idx] = l;
}

__global__ void xsplit_kernel(const float* __restrict__ x) {
    size_t idx = (size_t)blockIdx.x * blockDim.x + threadIdx.x;
    if (idx >= (size_t)NN * 128) return;
    float2 v = *reinterpret_cast<const float2*>(x + idx * 2);
    uint32_t h, l;
    splitbf2(v.x, v.y, h, l);
    g_ah[idx] = h;
    g_al[idx] = l;
}

// ---------------- fused aggregation (gather + self-loop + bias + relu + split)
__global__ void agg_d128_kernel(const float* __restrict__ bias) {
    int warp = (blockIdx.x * blockDim.x + threadIdx.x) >> 5;
    int lane = threadIdx.x & 31;
    if (warp >= NN) return;
    int rs = g_rowptr[warp], re = g_rowptr[warp + 1];
    float di = g_din[warp];
    float sc = di * di;
    float4 acc = *reinterpret_cast<const float4*>(g_h + (size_t)warp * 128 + lane * 4);
    acc.x *= sc; acc.y *= sc; acc.z *= sc; acc.w *= sc;
    for (int j = rs; j < re; j++) {
        int s = g_ssrc[j];
        float c = g_scoef[j];
        float4 v = *reinterpret_cast<const float4*>(g_h + (size_t)s * 128 + lane * 4);
        acc.x += v.x * c; acc.y += v.y * c; acc.z += v.z * c; acc.w += v.w * c;
    }
    float4 b = *reinterpret_cast<const float4*>(bias + lane * 4);
    acc.x = fmaxf(acc.x + b.x, 0.0f);
    acc.y = fmaxf(acc.y + b.y, 0.0f);
    acc.z = fmaxf(acc.z + b.z, 0.0f);
    acc.w = fmaxf(acc.w + b.w, 0.0f);
    uint32_t h0, l0, h1, l1;
    splitbf2(acc.x, acc.y, h0, l0);
    splitbf2(acc.z, acc.w, h1, l1);
    size_t o = (size_t)warp * 64 + lane * 2;
    g_ah[o] = h0; g_ah[o + 1] = h1;
    g_al[o] = l0; g_al[o + 1] = l1;
}

__global__ void agg_d64_kernel(const float* __restrict__ bias, float* __restrict__ zout) {
    int warp = (blockIdx.x * blockDim.x + threadIdx.x) >> 5;
    int lane = threadIdx.x & 31;
    if (warp >= NN) return;
    int rs = g_rowptr[warp], re = g_rowptr[warp + 1];
    float di = g_din[warp];
    float sc = di * di;
    float2 acc = *reinterpret_cast<const float2*>(g_h + (size_t)warp * 64 + lane * 2);
    acc.x *= sc; acc.y *= sc;
    for (int j = rs; j < re; j++) {
        int s = g_ssrc[j];
        float c = g_scoef[j];
        float2 v = *reinterpret_cast<const float2*>(g_h + (size_t)s * 64 + lane * 2);
        acc.x += v.x * c; acc.y += v.y * c;
    }
    float2 b = *reinterpret_cast<const float2*>(bias + lane * 2);
    acc.x += b.x; acc.y += b.y;
    *reinterpret_cast<float2*>(zout + (size_t)warp * 64 + lane * 2) = acc;
    uint32_t h, l;
    splitbf2(acc.x, acc.y, h, l);
    g_zh[(size_t)warp * 32 + lane] = h;
    g_zl[(size_t)warp * 32 + lane] = l;
}

// ---------------- BF16x3 tensor-core GEMM (pre-split inputs, no prefetch) ----
// C[N,M] = A[N,K] @ W[K,M]; A from g_ah/g_al (or g_zh/g_zl), W from g_wbh/g_wbl.
// block tile 128x64, 8 warps, warp tile 32x32; 32 k (16 packs) per stage.
// Inner loop: pure LDS + mma. No register double-buffer (avoids RF spills).
#define GBM 128
#define GBN 64
#define KPT 16    // packs per chunk
#define APAD 4    // A stride 20 u32: frag banks all distinct
#define BPAD 8    // B stride 72 u32: frag banks all distinct

__device__ __forceinline__ void mma_bf16(float c[4],
                                         uint32_t a0, uint32_t a1, uint32_t a2, uint32_t a3,
                                         uint32_t b0, uint32_t b1) {
    asm("mma.sync.aligned.m16n8k16.row.col.f32.bf16.bf16.f32 "
        "{%0,%1,%2,%3}, {%4,%5,%6,%7}, {%8,%9}, {%0,%1,%2,%3};"
        : "+f"(c[0]), "+f"(c[1]), "+f"(c[2]), "+f"(c[3])
        : "r"(a0), "r"(a1), "r"(a2), "r"(a3), "r"(b0), "r"(b1));
}

__global__ void __launch_bounds__(256, 2)
gemm_tc_kernel(int a_sel, int Kp, int wt_off,
               const float* __restrict__ bias,
               float* C_ext, int write_split,
               int M, int do_relu) {
    __shared__ uint32_t AsH[GBM][KPT + APAD];
    __shared__ uint32_t AsL[GBM][KPT + APAD];
    __shared__ uint32_t BsH[KPT][GBN + BPAD];
    __shared__ uint32_t BsL[KPT][GBN + BPAD];

    const uint32_t* Ah = a_sel ? g_zh : g_ah;
    const uint32_t* Al = a_sel ? g_zl : g_al;
    const uint32_t* WH = g_wbh + wt_off;
    const uint32_t* WL = g_wbl + wt_off;
    float* C = C_ext ? C_ext : g_h;

    int tid  = threadIdx.x;
    int wid  = tid >> 5;
    int lane = tid & 31;
    int wm   = wid & 3;
    int wn   = wid >> 2;
    int group = lane >> 2;
    int tig   = lane & 3;

    int row0 = blockIdx.y * GBM;
    int col0 = blockIdx.x * GBN;

    float acc[2][4][4];
#pragma unroll
    for (int mi = 0; mi < 2; mi++)
#pragma unroll
        for (int ni = 0; ni < 4; ni++)
#pragma unroll
            for (int q = 0; q < 4; q++) acc[mi][ni][q] = 0.0f;

    for (int k0p = 0; k0p < Kp; k0p += KPT) {
        // ---- load + store tile (short register live range; no spills) ----
#pragma unroll
        for (int q = 0; q < 2; q++) {
            int f4 = tid * 2 + q;          // 0..511
            int r  = f4 >> 2;
            int c4 = (f4 & 3) * 4;
            int gr = row0 + r;
            uint4 h = make_uint4(0, 0, 0, 0), l = make_uint4(0, 0, 0, 0);
            if (gr < NN) {
                h = *reinterpret_cast<const uint4*>(Ah + (size_t)gr * Kp + k0p + c4);
                l = *reinterpret_cast<const uint4*>(Al + (size_t)gr * Kp + k0p + c4);
            }
            *reinterpret_cast<uint4*>(&AsH[r][c4]) = h;
            *reinterpret_cast<uint4*>(&AsL[r][c4]) = l;
        }
        {
            int k2 = tid >> 4;             // 0..15
            int n4 = (tid & 15) * 4;
            uint4 h = *reinterpret_cast<const uint4*>(WH + (size_t)(k0p + k2) * M + col0 + n4);
            uint4 l = *reinterpret_cast<const uint4*>(WL + (size_t)(k0p + k2) * M + col0 + n4);
            *reinterpret_cast<uint4*>(&BsH[k2][n4]) = h;
            *reinterpret_cast<uint4*>(&BsL[k2][n4]) = l;
        }
        __syncthreads();

        // ---- compute ----
#pragma unroll
        for (int ks = 0; ks < 2; ks++) {
            int kb = ks * 8;
            uint32_t ahi[2][4], alo[2][4];
            uint32_t bhi[4][2], blo[4][2];
#pragma unroll
            for (int mi = 0; mi < 2; mi++) {
                int m = wm * 32 + mi * 16 + group;
                ahi[mi][0] = AsH[m    ][kb + tig];
                ahi[mi][1] = AsH[m + 8][kb + tig];
                ahi[mi][2] = AsH[m    ][kb + tig + 4];
                ahi[mi][3] = AsH[m + 8][kb + tig + 4];
                alo[mi][0] = AsL[m    ][kb + tig];
                alo[mi][1] = AsL[m + 8][kb + tig];
                alo[mi][2] = AsL[m    ][kb + tig + 4];
                alo[mi][3] = AsL[m + 8][kb + tig + 4];
            }
#pragma unroll
            for (int ni = 0; ni < 4; ni++) {
                int n = wn * 32 + ni * 8 + group;
                bhi[ni][0] = BsH[kb + tig    ][n];
                bhi[ni][1] = BsH[kb + tig + 4][n];
                blo[ni][0] = BsL[kb + tig    ][n];
                blo[ni][1] = BsL[kb + tig + 4][n];
            }
#pragma unroll
            for (int ni = 0; ni < 4; ni++)
#pragma unroll
                for (int mi = 0; mi < 2; mi++)
                    mma_bf16(acc[mi][ni], ahi[mi][0], ahi[mi][1], ahi[mi][2], ahi[mi][3],
                             bhi[ni][0], bhi[ni][1]);
#pragma unroll
            for (int ni = 0; ni < 4; ni++)
#pragma unroll
                for (int mi = 0; mi < 2; mi++)
                    mma_bf16(acc[mi][ni], ahi[mi][0], ahi[mi][1], ahi[mi][2], ahi[mi][3],
                             blo[ni][0], blo[ni][1]);
#pragma unroll
            for (int ni = 0; ni < 4; ni++)
#pragma unroll
                for (int mi = 0; mi < 2; mi++)
                    mma_bf16(acc[mi][ni], alo[mi][0], alo[mi][1], alo[mi][2], alo[mi][3],
                             bhi[ni][0], bhi[ni][1]);
        }
        __syncthreads();
    }

    // ---- epilogue ----
#pragma unroll
    for (int mi = 0; mi < 2; mi++) {
#pragma unroll
        for (int ni = 0; ni < 4; ni++) {
            int colb = col0 + wn * 32 + ni * 8 + tig * 2;
            float b0 = 0.f, b1 = 0.f;
            if (bias) { b0 = bias[colb]; b1 = bias[colb + 1]; }
#pragma unroll
            for (int half = 0; half < 2; half++) {
                int r = row0 + wm * 32 + mi * 16 + group + half * 8;
                if (r >= NN) continue;
                float v0 = acc[mi][ni][half * 2 + 0] + b0;
                float v1 = acc[mi][ni][half * 2 + 1] + b1;
                if (do_relu) { v0 = fmaxf(v0, 0.f); v1 = fmaxf(v1, 0.f); }
                if (write_split) {
                    uint32_t h, l;
                    splitbf2(v0, v1, h, l);
                    size_t o = (size_t)r * (M >> 1) + (colb >> 1);
                    g_ah[o] = h;
                    g_al[o] = l;
                } else {
                    *reinterpret_cast<float2*>(C + (size_t)r * M + colb) = make_float2(v0, v1);
                }
            }
        }
    }
}

// ---------------- orchestration ----------------------------------------------
static inline void run_gemm(int a_sel, int Kp, int wt_off, const float* bias,
                            float* C_ext, int write_split, int M, int relu) {
    dim3 grid(M / GBN, (NN + GBM - 1) / GBM);
    gemm_tc_kernel<<<grid, 256>>>(a_sel, Kp, wt_off, bias, C_ext, write_split, M, relu);
}

extern "C" void kernel_launch(void* const* d_in, const int* in_sizes, int n_in,
                              void* d_out, int out_size) {
    const float* x   = (const float*)d_in[0];
    const void*  ei  = d_in[1];
    const float* W1  = (const float*)d_in[2];
    const float* b1  = (const float*)d_in[3];
    const float* W2  = (const float*)d_in[4];
    const float* b2  = (const float*)d_in[5];
    const float* W3  = (const float*)d_in[6];
    const float* b3  = (const float*)d_in[7];
    const float* Wd1 = (const float*)d_in[8];
    const float* bd1 = (const float*)d_in[9];
    const float* Wd2 = (const float*)d_in[10];
    const float* bd2 = (const float*)d_in[11];

    float* z    = (float*)d_out;                     // [N, 64]
    float* xhat = (float*)d_out + (size_t)NN * DE;   // [N, 256]

    // ---- graph preprocessing + pre-splitting ----------------------------
    detect_kernel<<<1, 32>>>((const int*)ei);
    zero_cnt_kernel<<<(NN + 255) / 256, 256>>>();
    convert_kernel<<<(2 * EE + 255) / 256, 256>>>(ei);
    scan1_kernel<<<NB, 1024>>>();
    scan2_kernel<<<1, 32>>>();
    scan3_kernel<<<(NN + 255) / 256, 256>>>();
    fill_csr_kernel<<<(EE + 255) / 256, 256>>>();
    wsplit_kernel<<<(WPACKS + 255) / 256, 256>>>(W1, W2, W3, Wd1, Wd2);
    xsplit_kernel<<<(int)(((size_t)NN * 128 + 255) / 256), 256>>>(x);

    int aggBlocks = (NN + 7) / 8;

    // ---- layer 1: h1 = relu(gcn(x, W1, b1)) -----------------------------
    run_gemm(0, 128, OFF_W1, nullptr, nullptr, 0, DH, 0);   // g_h = x@W1
    agg_d128_kernel<<<aggBlocks, 256>>>(b1);                // -> split in g_ah/g_al

    // ---- layer 2: h2 = relu(gcn(h1, W2, b2)) ----------------------------
    run_gemm(0, 64, OFF_W2, nullptr, nullptr, 0, DH, 0);
    agg_d128_kernel<<<aggBlocks, 256>>>(b2);

    // ---- layer 3: z = gcn(h2, W3, b3) -----------------------------------
    run_gemm(0, 64, OFF_W3, nullptr, nullptr, 0, DE, 0);
    agg_d64_kernel<<<aggBlocks, 256>>>(b3, z);              // z f32 + split in g_zh/zl

    // ---- decoder: x_hat = relu(z@Wd1+bd1)@Wd2 + bd2 ---------------------
    run_gemm(1, 32, OFF_WD1, bd1, nullptr, 1, DH, 1);       // split h -> g_ah/g_al
    run_gemm(0, 64, OFF_WD2, bd2, xhat, 0, DIN, 0);
}

// round 14
// speedup vs baseline: 1.5693x; 1.1914x over previous
#include <cuda_runtime.h>
#include <cuda_bf16.h>
#include <math.h>
#include <stdint.h>

#define NN 100000
#define EE 600000
#define DIN 256
#define DH  128
#define DE  64
#define NB  ((NN + 1023) / 1024)

// weight pack offsets (u32 packs, [k2][M] layout per segment)
#define OFF_W1  0        // Kp=128, M=128
#define OFF_W2  16384    // Kp=64,  M=128
#define OFF_W3  24576    // Kp=64,  M=64
#define OFF_WD1 28672    // Kp=32,  M=128
#define OFF_WD2 32768    // Kp=64,  M=256
#define WPACKS  49152

// ---------------- scratch (static device globals; no allocation) ------------
__device__ float    g_h  [(size_t)NN * DH];   // GEMM f32 output (pre-agg)
__device__ uint32_t g_ah [(size_t)NN * 128];  // activation split hi (bf16x2 packs)
__device__ uint32_t g_al [(size_t)NN * 128];  // activation split lo
__device__ uint32_t g_zh [(size_t)NN * 32];   // z split hi
__device__ uint32_t g_zl [(size_t)NN * 32];   // z split lo
__device__ uint32_t g_wbh[WPACKS];            // weight split hi
__device__ uint32_t g_wbl[WPACKS];            // weight split lo
__device__ float    g_din[NN];
__device__ int      g_cnt[NN];
__device__ int      g_rowptr[NN + 1];
__device__ int      g_cur[NN];
__device__ int      g_bsum[NB];
__device__ int      g_ssrc [EE];
__device__ float    g_scoef[EE];
__device__ int      g_src[EE];
__device__ int      g_dst[EE];
__device__ int      g_is64;

// split f0,f1 -> packed bf16x2 hi / lo
__device__ __forceinline__ void splitbf2(float f0, float f1, uint32_t& hi, uint32_t& lo) {
    __nv_bfloat162 h = __floats2bfloat162_rn(f0, f1);
    float r0 = f0 - __bfloat162float(h.x);
    float r1 = f1 - __bfloat162float(h.y);
    __nv_bfloat162 l = __floats2bfloat162_rn(r0, r1);
    hi = *reinterpret_cast<uint32_t*>(&h);
    lo = *reinterpret_cast<uint32_t*>(&l);
}

// ---------------- edge-index dtype detection + conversion -------------------
__global__ void detect_kernel(const int* __restrict__ w) {
    if (threadIdx.x == 0 && blockIdx.x == 0) {
        int is64 = 1;
        for (int i = 1; i < 128; i += 2)
            if (w[i] != 0) { is64 = 0; break; }
        g_is64 = is64;
    }
}

__global__ void convert_kernel(const void* __restrict__ ei) {
    int e = blockIdx.x * blockDim.x + threadIdx.x;
    if (e >= 2 * EE) return;
    int v;
    if (g_is64) v = (int)((const long long*)ei)[e];
    else        v = ((const int*)ei)[e];
    v = max(0, min(NN - 1, v));
    if (e < EE) g_src[e] = v;
    else        { g_dst[e - EE] = v; atomicAdd(&g_cnt[v], 1); }
}

__global__ void zero_cnt_kernel() {
    int i = blockIdx.x * blockDim.x + threadIdx.x;
    if (i < NN) g_cnt[i] = 0;
}

__global__ void scan1_kernel() {
    __shared__ int s[1024];
    int i = blockIdx.x * 1024 + threadIdx.x;
    int v = (i < NN) ? g_cnt[i] : 0;
    if (i < NN) g_din[i] = rsqrtf((float)v + 1.0f);
    s[threadIdx.x] = v;
    __syncthreads();
    for (int off = 1; off < 1024; off <<= 1) {
        int t = (threadIdx.x >= off) ? s[threadIdx.x - off] : 0;
        __syncthreads();
        s[threadIdx.x] += t;
        __syncthreads();
    }
    if (i < NN) g_rowptr[i + 1] = s[threadIdx.x];
    if (threadIdx.x == 1023) g_bsum[blockIdx.x] = s[1023];
}

__global__ void scan2_kernel() {
    if (threadIdx.x == 0 && blockIdx.x == 0) {
        int run = 0;
        for (int b = 0; b < NB; b++) { int t = g_bsum[b]; g_bsum[b] = run; run += t; }
        g_rowptr[0] = 0;
    }
}

__global__ void scan3_kernel() {
    int i = blockIdx.x * blockDim.x + threadIdx.x;
    if (i < NN) {
        int v = g_rowptr[i + 1] + g_bsum[i >> 10];
        g_rowptr[i + 1] = v;
        g_cur[i] = v - g_cnt[i];
    }
}

__global__ void fill_csr_kernel() {
    int e = blockIdx.x * blockDim.x + threadIdx.x;
    if (e >= EE) return;
    int s = g_src[e];
    int d = g_dst[e];
    int slot = atomicAdd(&g_cur[d], 1);
    g_ssrc[slot]  = s;
    g_scoef[slot] = g_din[s] * g_din[d];
}

// ---------------- pre-split kernels -------------------------------------------
__global__ void wsplit_kernel(const float* __restrict__ W1, const float* __restrict__ W2,
                              const float* __restrict__ W3, const float* __restrict__ Wd1,
                              const float* __restrict__ Wd2) {
    int idx = blockIdx.x * blockDim.x + threadIdx.x;
    if (idx >= WPACKS) return;
    const float* W; int M, off;
    if      (idx < OFF_W2)  { W = W1;  M = 128; off = OFF_W1; }
    else if (idx < OFF_W3)  { W = W2;  M = 128; off = OFF_W2; }
    else if (idx < OFF_WD1) { W = W3;  M = 64;  off = OFF_W3; }
    else if (idx < OFF_WD2) { W = Wd1; M = 128; off = OFF_WD1; }
    else                    { W = Wd2; M = 256; off = OFF_WD2; }
    int local = idx - off;
    int k2 = local / M, m = local - k2 * M;
    uint32_t h, l;
    splitbf2(W[(2 * k2) * M + m], W[(2 * k2 + 1) * M + m], h, l);
    g_wbh[idx] = h;
    g_wbl[idx] = l;
}

__global__ void xsplit_kernel(const float* __restrict__ x) {
    size_t idx = (size_t)blockIdx.x * blockDim.x + threadIdx.x;
    if (idx >= (size_t)NN * 128) return;
    float2 v = *reinterpret_cast<const float2*>(x + idx * 2);
    uint32_t h, l;
    splitbf2(v.x, v.y, h, l);
    g_ah[idx] = h;
    g_al[idx] = l;
}

// ---------------- fused aggregation (gather + self-loop + bias + relu + split)
__global__ void agg_d128_kernel(const float* __restrict__ bias) {
    int warp = (blockIdx.x * blockDim.x + threadIdx.x) >> 5;
    int lane = threadIdx.x & 31;
    if (warp >= NN) return;
    int rs = g_rowptr[warp], re = g_rowptr[warp + 1];
    float di = g_din[warp];
    float sc = di * di;
    float4 acc = *reinterpret_cast<const float4*>(g_h + (size_t)warp * 128 + lane * 4);
    acc.x *= sc; acc.y *= sc; acc.z *= sc; acc.w *= sc;
    for (int j = rs; j < re; j++) {
        int s = g_ssrc[j];
        float c = g_scoef[j];
        float4 v = *reinterpret_cast<const float4*>(g_h + (size_t)s * 128 + lane * 4);
        acc.x += v.x * c; acc.y += v.y * c; acc.z += v.z * c; acc.w += v.w * c;
    }
    float4 b = *reinterpret_cast<const float4*>(bias + lane * 4);
    acc.x = fmaxf(acc.x + b.x, 0.0f);
    acc.y = fmaxf(acc.y + b.y, 0.0f);
    acc.z = fmaxf(acc.z + b.z, 0.0f);
    acc.w = fmaxf(acc.w + b.w, 0.0f);
    uint32_t h0, l0, h1, l1;
    splitbf2(acc.x, acc.y, h0, l0);
    splitbf2(acc.z, acc.w, h1, l1);
    size_t o = (size_t)warp * 64 + lane * 2;
    g_ah[o] = h0; g_ah[o + 1] = h1;
    g_al[o] = l0; g_al[o + 1] = l1;
}

__global__ void agg_d64_kernel(const float* __restrict__ bias, float* __restrict__ zout) {
    int warp = (blockIdx.x * blockDim.x + threadIdx.x) >> 5;
    int lane = threadIdx.x & 31;
    if (warp >= NN) return;
    int rs = g_rowptr[warp], re = g_rowptr[warp + 1];
    float di = g_din[warp];
    float sc = di * di;
    float2 acc = *reinterpret_cast<const float2*>(g_h + (size_t)warp * 64 + lane * 2);
    acc.x *= sc; acc.y *= sc;
    for (int j = rs; j < re; j++) {
        int s = g_ssrc[j];
        float c = g_scoef[j];
        float2 v = *reinterpret_cast<const float2*>(g_h + (size_t)s * 64 + lane * 2);
        acc.x += v.x * c; acc.y += v.y * c;
    }
    float2 b = *reinterpret_cast<const float2*>(bias + lane * 2);
    acc.x += b.x; acc.y += b.y;
    *reinterpret_cast<float2*>(zout + (size_t)warp * 64 + lane * 2) = acc;
    uint32_t h, l;
    splitbf2(acc.x, acc.y, h, l);
    g_zh[(size_t)warp * 32 + lane] = h;
    g_zl[(size_t)warp * 32 + lane] = l;
}

// ---------------- BF16x3 GEMM with cp.async double-buffer --------------------
// C[N,M] = A[N,K] @ W[K,M]; A from g_ah/g_al (or g_zh/g_zl), W from g_wbh/g_wbl.
// block tile 128x64, 8 warps, warp tile 32x32; 32 k (16 packs) per stage.
// cp.async gmem->smem (no register staging), 2 smem stages.
#define GBM 128
#define GBN 64
#define KPT 16      // packs per chunk
#define ASTR 20     // A row stride (u32): frag banks all distinct
#define BSTR 72     // B row stride (u32): frag banks all distinct
#define AOFF_L 2560           // 128*20
#define BOFF_H 5120
#define BOFF_L 6272           // +16*72
#define SSZ    7424           // u32 per stage
#define GEMM_SMEM (2 * SSZ * 4)

__device__ __forceinline__ void cp_async16(uint32_t saddr, const void* gptr, int src_bytes) {
    asm volatile("cp.async.cg.shared.global [%0], [%1], 16, %2;"
                 :: "r"(saddr), "l"(gptr), "r"(src_bytes));
}

__device__ __forceinline__ void mma_bf16(float c[4],
                                         uint32_t a0, uint32_t a1, uint32_t a2, uint32_t a3,
                                         uint32_t b0, uint32_t b1) {
    asm("mma.sync.aligned.m16n8k16.row.col.f32.bf16.bf16.f32 "
        "{%0,%1,%2,%3}, {%4,%5,%6,%7}, {%8,%9}, {%0,%1,%2,%3};"
        : "+f"(c[0]), "+f"(c[1]), "+f"(c[2]), "+f"(c[3])
        : "r"(a0), "r"(a1), "r"(a2), "r"(a3), "r"(b0), "r"(b1));
}

__global__ void __launch_bounds__(256, 2)
gemm_tc_kernel(int a_sel, int Kp, int wt_off,
               const float* __restrict__ bias,
               float* C_ext, int write_split,
               int M, int do_relu) {
    extern __shared__ uint32_t ds[];
    uint32_t sb = (uint32_t)__cvta_generic_to_shared(ds);

    const uint32_t* Ah = a_sel ? g_zh : g_ah;
    const uint32_t* Al = a_sel ? g_zl : g_al;
    const uint32_t* WH = g_wbh + wt_off;
    const uint32_t* WL = g_wbl + wt_off;
    float* C = C_ext ? C_ext : g_h;

    int tid  = threadIdx.x;
    int wid  = tid >> 5;
    int lane = tid & 31;
    int wm   = wid & 3;
    int wn   = wid >> 2;
    int group = lane >> 2;
    int tig   = lane & 3;

    int row0 = blockIdx.y * GBM;
    int col0 = blockIdx.x * GBN;

    float acc[2][4][4];
#pragma unroll
    for (int mi = 0; mi < 2; mi++)
#pragma unroll
        for (int ni = 0; ni < 4; ni++)
#pragma unroll
            for (int q = 0; q < 4; q++) acc[mi][ni][q] = 0.0f;

    int nch = Kp / KPT;

    auto issueLoads = [&](int c, int buf) {
        int k0p = c * KPT;
        uint32_t base = sb + (uint32_t)buf * SSZ * 4;
#pragma unroll
        for (int q = 0; q < 2; q++) {
            int f4 = tid * 2 + q;          // 0..511
            int r  = f4 >> 2;
            int c4 = (f4 & 3) * 4;
            int gr = row0 + r;
            int ok = (gr < NN) ? 16 : 0;
            int grc = (gr < NN) ? gr : (NN - 1);
            cp_async16(base + (r * ASTR + c4) * 4,
                       Ah + (size_t)grc * Kp + k0p + c4, ok);
            cp_async16(base + (AOFF_L + r * ASTR + c4) * 4,
                       Al + (size_t)grc * Kp + k0p + c4, ok);
        }
        {
            int k2 = tid >> 4;             // 0..15
            int n4 = (tid & 15) * 4;
            cp_async16(base + (BOFF_H + k2 * BSTR + n4) * 4,
                       WH + (size_t)(k0p + k2) * M + col0 + n4, 16);
            cp_async16(base + (BOFF_L + k2 * BSTR + n4) * 4,
                       WL + (size_t)(k0p + k2) * M + col0 + n4, 16);
        }
        asm volatile("cp.async.commit_group;");
    };

    auto compute = [&](int buf) {
        const uint32_t* AsH = ds + buf * SSZ;
        const uint32_t* AsL = AsH + AOFF_L;
        const uint32_t* BsH = ds + buf * SSZ + BOFF_H;
        const uint32_t* BsL = ds + buf * SSZ + BOFF_L;
#pragma unroll
        for (int ks = 0; ks < 2; ks++) {
            int kb = ks * 8;
            uint32_t ahi[2][4], alo[2][4];
            uint32_t bhi[4][2], blo[4][2];
#pragma unroll
            for (int mi = 0; mi < 2; mi++) {
                int m = wm * 32 + mi * 16 + group;
                ahi[mi][0] = AsH[(m    ) * ASTR + kb + tig];
                ahi[mi][1] = AsH[(m + 8) * ASTR + kb + tig];
                ahi[mi][2] = AsH[(m    ) * ASTR + kb + tig + 4];
                ahi[mi][3] = AsH[(m + 8) * ASTR + kb + tig + 4];
                alo[mi][0] = AsL[(m    ) * ASTR + kb + tig];
                alo[mi][1] = AsL[(m + 8) * ASTR + kb + tig];
                alo[mi][2] = AsL[(m    ) * ASTR + kb + tig + 4];
                alo[mi][3] = AsL[(m + 8) * ASTR + kb + tig + 4];
            }
#pragma unroll
            for (int ni = 0; ni < 4; ni++) {
                int n = wn * 32 + ni * 8 + group;
                bhi[ni][0] = BsH[(kb + tig    ) * BSTR + n];
                bhi[ni][1] = BsH[(kb + tig + 4) * BSTR + n];
                blo[ni][0] = BsL[(kb + tig    ) * BSTR + n];
                blo[ni][1] = BsL[(kb + tig + 4) * BSTR + n];
            }
#pragma unroll
            for (int ni = 0; ni < 4; ni++)
#pragma unroll
                for (int mi = 0; mi < 2; mi++)
                    mma_bf16(acc[mi][ni], ahi[mi][0], ahi[mi][1], ahi[mi][2], ahi[mi][3],
                             bhi[ni][0], bhi[ni][1]);
#pragma unroll
            for (int ni = 0; ni < 4; ni++)
#pragma unroll
                for (int mi = 0; mi < 2; mi++)
                    mma_bf16(acc[mi][ni], ahi[mi][0], ahi[mi][1], ahi[mi][2], ahi[mi][3],
                             blo[ni][0], blo[ni][1]);
#pragma unroll
            for (int ni = 0; ni < 4; ni++)
#pragma unroll
                for (int mi = 0; mi < 2; mi++)
                    mma_bf16(acc[mi][ni], alo[mi][0], alo[mi][1], alo[mi][2], alo[mi][3],
                             bhi[ni][0], bhi[ni][1]);
        }
    };

    issueLoads(0, 0);
    for (int c = 0; c < nch; c++) {
        int buf = c & 1;
        if (c + 1 < nch) {
            issueLoads(c + 1, buf ^ 1);
            asm volatile("cp.async.wait_group 1;");
        } else {
            asm volatile("cp.async.wait_group 0;");
        }
        __syncthreads();
        compute(buf);
        __syncthreads();
    }

    // ---- epilogue ----
#pragma unroll
    for (int mi = 0; mi < 2; mi++) {
#pragma unroll
        for (int ni = 0; ni < 4; ni++) {
            int colb = col0 + wn * 32 + ni * 8 + tig * 2;
            float b0 = 0.f, b1 = 0.f;
            if (bias) { b0 = bias[colb]; b1 = bias[colb + 1]; }
#pragma unroll
            for (int half = 0; half < 2; half++) {
                int r = row0 + wm * 32 + mi * 16 + group + half * 8;
                if (r >= NN) continue;
                float v0 = acc[mi][ni][half * 2 + 0] + b0;
                float v1 = acc[mi][ni][half * 2 + 1] + b1;
                if (do_relu) { v0 = fmaxf(v0, 0.f); v1 = fmaxf(v1, 0.f); }
                if (write_split) {
                    uint32_t h, l;
                    splitbf2(v0, v1, h, l);
                    size_t o = (size_t)r * (M >> 1) + (colb >> 1);
                    g_ah[o] = h;
                    g_al[o] = l;
                } else {
                    *reinterpret_cast<float2*>(C + (size_t)r * M + colb) = make_float2(v0, v1);
                }
            }
        }
    }
}

// ---------------- orchestration ----------------------------------------------
static inline void run_gemm(int a_sel, int Kp, int wt_off, const float* bias,
                            float* C_ext, int write_split, int M, int relu) {
    dim3 grid(M / GBN, (NN + GBM - 1) / GBM);
    gemm_tc_kernel<<<grid, 256, GEMM_SMEM>>>(a_sel, Kp, wt_off, bias, C_ext,
                                             write_split, M, relu);
}

extern "C" void kernel_launch(void* const* d_in, const int* in_sizes, int n_in,
                              void* d_out, int out_size) {
    const float* x   = (const float*)d_in[0];
    const void*  ei  = d_in[1];
    const float* W1  = (const float*)d_in[2];
    const float* b1  = (const float*)d_in[3];
    const float* W2  = (const float*)d_in[4];
    const float* b2  = (const float*)d_in[5];
    const float* W3  = (const float*)d_in[6];
    const float* b3  = (const float*)d_in[7];
    const float* Wd1 = (const float*)d_in[8];
    const float* bd1 = (const float*)d_in[9];
    const float* Wd2 = (const float*)d_in[10];
    const float* bd2 = (const float*)d_in[11];

    float* z    = (float*)d_out;                     // [N, 64]
    float* xhat = (float*)d_out + (size_t)NN * DE;   // [N, 256]

    cudaFuncSetAttribute(gemm_tc_kernel,
                         cudaFuncAttributeMaxDynamicSharedMemorySize, GEMM_SMEM);

    // ---- graph preprocessing + pre-splitting ----------------------------
    detect_kernel<<<1, 32>>>((const int*)ei);
    zero_cnt_kernel<<<(NN + 255) / 256, 256>>>();
    convert_kernel<<<(2 * EE + 255) / 256, 256>>>(ei);
    scan1_kernel<<<NB, 1024>>>();
    scan2_kernel<<<1, 32>>>();
    scan3_kernel<<<(NN + 255) / 256, 256>>>();
    fill_csr_kernel<<<(EE + 255) / 256, 256>>>();
    wsplit_kernel<<<(WPACKS + 255) / 256, 256>>>(W1, W2, W3, Wd1, Wd2);
    xsplit_kernel<<<(int)(((size_t)NN * 128 + 255) / 256), 256>>>(x);

    int aggBlocks = (NN + 7) / 8;

    // ---- layer 1: h1 = relu(gcn(x, W1, b1)) -----------------------------
    run_gemm(0, 128, OFF_W1, nullptr, nullptr, 0, DH, 0);   // g_h = x@W1
    agg_d128_kernel<<<aggBlocks, 256>>>(b1);                // -> split in g_ah/g_al

    // ---- layer 2: h2 = relu(gcn(h1, W2, b2)) ----------------------------
    run_gemm(0, 64, OFF_W2, nullptr, nullptr, 0, DH, 0);
    agg_d128_kernel<<<aggBlocks, 256>>>(b2);

    // ---- layer 3: z = gcn(h2, W3, b3) -----------------------------------
    run_gemm(0, 64, OFF_W3, nullptr, nullptr, 0, DE, 0);
    agg_d64_kernel<<<aggBlocks, 256>>>(b3, z);              // z f32 + split in g_zh/zl

    // ---- decoder: x_hat = relu(z@Wd1+bd1)@Wd2 + bd2 ---------------------
    run_gemm(1, 32, OFF_WD1, bd1, nullptr, 1, DH, 1);       // split h -> g_ah/g_al
    run_gemm(0, 64, OFF_WD2, bd2, xhat, 0, DIN, 0);
}

// round 15
// speedup vs baseline: 1.8442x; 1.1752x over previous
#include <cuda_runtime.h>
#include <cuda_bf16.h>
#include <math.h>
#include <stdint.h>

#define NN 100000
#define EE 600000
#define DIN 256
#define DH  128
#define DE  64
#define NB  ((NN + 1023) / 1024)

// weight pack offsets (u32 packs, [k2][M] layout per segment)
#define OFF_W1  0        // Kp=128, M=128
#define OFF_W2  16384    // Kp=64,  M=128
#define OFF_W3  24576    // Kp=64,  M=64
#define OFF_WD1 28672    // Kp=32,  M=128
#define OFF_WD2 32768    // Kp=64,  M=256
#define WPACKS  49152

// ---------------- scratch (static device globals; no allocation) ------------
__device__ float    g_h  [(size_t)NN * DH];   // GEMM f32 output (pre-agg)
__device__ uint32_t g_ah [(size_t)NN * 128];  // activation split hi (bf16x2 packs)
__device__ uint32_t g_al [(size_t)NN * 128];  // activation split lo
__device__ uint32_t g_zh [(size_t)NN * 32];   // z split hi
__device__ uint32_t g_zl [(size_t)NN * 32];   // z split lo
__device__ uint32_t g_wbh[WPACKS];            // weight split hi
__device__ uint32_t g_wbl[WPACKS];            // weight split lo
__device__ float    g_din[NN];
__device__ int      g_cnt[NN];
__device__ int      g_rowptr[NN + 1];
__device__ int      g_cur[NN];
__device__ int      g_bsum[NB];
__device__ int      g_ssrc [EE];
__device__ float    g_scoef[EE];
__device__ int      g_src[EE];
__device__ int      g_dst[EE];
__device__ int      g_is64;

// split f0,f1 -> packed bf16x2 hi / lo
__device__ __forceinline__ void splitbf2(float f0, float f1, uint32_t& hi, uint32_t& lo) {
    __nv_bfloat162 h = __floats2bfloat162_rn(f0, f1);
    float r0 = f0 - __bfloat162float(h.x);
    float r1 = f1 - __bfloat162float(h.y);
    __nv_bfloat162 l = __floats2bfloat162_rn(r0, r1);
    hi = *reinterpret_cast<uint32_t*>(&h);
    lo = *reinterpret_cast<uint32_t*>(&l);
}

// ---------------- edge-index dtype detection + conversion -------------------
__global__ void detect_kernel(const int* __restrict__ w) {
    if (threadIdx.x == 0 && blockIdx.x == 0) {
        int is64 = 1;
        for (int i = 1; i < 128; i += 2)
            if (w[i] != 0) { is64 = 0; break; }
        g_is64 = is64;
    }
}

__global__ void convert_kernel(const void* __restrict__ ei) {
    int e = blockIdx.x * blockDim.x + threadIdx.x;
    if (e >= 2 * EE) return;
    int v;
    if (g_is64) v = (int)((const long long*)ei)[e];
    else        v = ((const int*)ei)[e];
    v = max(0, min(NN - 1, v));
    if (e < EE) g_src[e] = v;
    else        { g_dst[e - EE] = v; atomicAdd(&g_cnt[v], 1); }
}

__global__ void zero_cnt_kernel() {
    int i = blockIdx.x * blockDim.x + threadIdx.x;
    if (i < NN) g_cnt[i] = 0;
}

__global__ void scan1_kernel() {
    __shared__ int s[1024];
    int i = blockIdx.x * 1024 + threadIdx.x;
    int v = (i < NN) ? g_cnt[i] : 0;
    if (i < NN) g_din[i] = rsqrtf((float)v + 1.0f);
    s[threadIdx.x] = v;
    __syncthreads();
    for (int off = 1; off < 1024; off <<= 1) {
        int t = (threadIdx.x >= off) ? s[threadIdx.x - off] : 0;
        __syncthreads();
        s[threadIdx.x] += t;
        __syncthreads();
    }
    if (i < NN) g_rowptr[i + 1] = s[threadIdx.x];
    if (threadIdx.x == 1023) g_bsum[blockIdx.x] = s[1023];
}

__global__ void scan2_kernel() {
    if (threadIdx.x == 0 && blockIdx.x == 0) {
        int run = 0;
        for (int b = 0; b < NB; b++) { int t = g_bsum[b]; g_bsum[b] = run; run += t; }
        g_rowptr[0] = 0;
    }
}

__global__ void scan3_kernel() {
    int i = blockIdx.x * blockDim.x + threadIdx.x;
    if (i < NN) {
        int v = g_rowptr[i + 1] + g_bsum[i >> 10];
        g_rowptr[i + 1] = v;
        g_cur[i] = v - g_cnt[i];
    }
}

__global__ void fill_csr_kernel() {
    int e = blockIdx.x * blockDim.x + threadIdx.x;
    if (e >= EE) return;
    int s = g_src[e];
    int d = g_dst[e];
    int slot = atomicAdd(&g_cur[d], 1);
    g_ssrc[slot]  = s;
    g_scoef[slot] = g_din[s] * g_din[d];
}

// ---------------- weight pre-split -------------------------------------------
__global__ void wsplit_kernel(const float* __restrict__ W1, const float* __restrict__ W2,
                              const float* __restrict__ W3, const float* __restrict__ Wd1,
                              const float* __restrict__ Wd2) {
    int idx = blockIdx.x * blockDim.x + threadIdx.x;
    if (idx >= WPACKS) return;
    const float* W; int M, off;
    if      (idx < OFF_W2)  { W = W1;  M = 128; off = OFF_W1; }
    else if (idx < OFF_W3)  { W = W2;  M = 128; off = OFF_W2; }
    else if (idx < OFF_WD1) { W = W3;  M = 64;  off = OFF_W3; }
    else if (idx < OFF_WD2) { W = Wd1; M = 128; off = OFF_WD1; }
    else                    { W = Wd2; M = 256; off = OFF_WD2; }
    int local = idx - off;
    int k2 = local / M, m = local - k2 * M;
    uint32_t h, l;
    splitbf2(W[(2 * k2) * M + m], W[(2 * k2 + 1) * M + m], h, l);
    g_wbh[idx] = h;
    g_wbl[idx] = l;
}

// ---------------- fused aggregation (gather + self-loop + bias + relu + split)
__global__ void agg_d128_kernel(const float* __restrict__ bias) {
    int warp = (blockIdx.x * blockDim.x + threadIdx.x) >> 5;
    int lane = threadIdx.x & 31;
    if (warp >= NN) return;
    int rs = g_rowptr[warp], re = g_rowptr[warp + 1];
    float di = g_din[warp];
    float sc = di * di;
    float4 acc = *reinterpret_cast<const float4*>(g_h + (size_t)warp * 128 + lane * 4);
    acc.x *= sc; acc.y *= sc; acc.z *= sc; acc.w *= sc;
    for (int j = rs; j < re; j++) {
        int s = g_ssrc[j];
        float c = g_scoef[j];
        float4 v = *reinterpret_cast<const float4*>(g_h + (size_t)s * 128 + lane * 4);
        acc.x += v.x * c; acc.y += v.y * c; acc.z += v.z * c; acc.w += v.w * c;
    }
    float4 b = *reinterpret_cast<const float4*>(bias + lane * 4);
    acc.x = fmaxf(acc.x + b.x, 0.0f);
    acc.y = fmaxf(acc.y + b.y, 0.0f);
    acc.z = fmaxf(acc.z + b.z, 0.0f);
    acc.w = fmaxf(acc.w + b.w, 0.0f);
    uint32_t h0, l0, h1, l1;
    splitbf2(acc.x, acc.y, h0, l0);
    splitbf2(acc.z, acc.w, h1, l1);
    size_t o = (size_t)warp * 64 + lane * 2;
    g_ah[o] = h0; g_ah[o + 1] = h1;
    g_al[o] = l0; g_al[o + 1] = l1;
}

__global__ void agg_d64_kernel(const float* __restrict__ bias, float* __restrict__ zout) {
    int warp = (blockIdx.x * blockDim.x + threadIdx.x) >> 5;
    int lane = threadIdx.x & 31;
    if (warp >= NN) return;
    int rs = g_rowptr[warp], re = g_rowptr[warp + 1];
    float di = g_din[warp];
    float sc = di * di;
    float2 acc = *reinterpret_cast<const float2*>(g_h + (size_t)warp * 64 + lane * 2);
    acc.x *= sc; acc.y *= sc;
    for (int j = rs; j < re; j++) {
        int s = g_ssrc[j];
        float c = g_scoef[j];
        float2 v = *reinterpret_cast<const float2*>(g_h + (size_t)s * 64 + lane * 2);
        acc.x += v.x * c; acc.y += v.y * c;
    }
    float2 b = *reinterpret_cast<const float2*>(bias + lane * 2);
    acc.x += b.x; acc.y += b.y;
    *reinterpret_cast<float2*>(zout + (size_t)warp * 64 + lane * 2) = acc;
    uint32_t h, l;
    splitbf2(acc.x, acc.y, h, l);
    g_zh[(size_t)warp * 32 + lane] = h;
    g_zl[(size_t)warp * 32 + lane] = l;
}

// ---------------- BF16x3 GEMM with cp.async pipelines ------------------------
// a_sel: 0 = g_ah/g_al, 1 = g_zh/g_zl (3-stage ring), 2 = raw f32 x (fused split,
// 2-stage). block tile 128x64, 8 warps, warp tile 32x32; 32 k (16 packs)/chunk.
#define GBM 128
#define GBN 64
#define KPT 16      // packs per chunk
#define ASTR 20     // A row stride (u32): frag banks all distinct
#define BSTR 72     // B row stride (u32): frag banks all distinct
#define AOFF_L 2560            // 128*20
#define BOFF_H 5120
#define BOFF_L 6272            // +16*72
#define SSZ    7424            // u32 per stage (modes 0/1)
// mode 2 layout: [Af32 4096][AsH 2560][AsL 2560][BsH 1152][BsL 1152]
#define M2_AH  4096
#define M2_AL  6656
#define M2_BH  9216
#define M2_BL  10368
#define S2SZ   11520
#define GEMM_SMEM_01 (3 * SSZ * 4)     // 89088
#define GEMM_SMEM_2  (2 * S2SZ * 4)    // 92160
#define GEMM_SMEM_MAX GEMM_SMEM_2

__device__ __forceinline__ void cp_async16(uint32_t saddr, const void* gptr, int src_bytes) {
    asm volatile("cp.async.cg.shared.global [%0], [%1], 16, %2;"
                 :: "r"(saddr), "l"(gptr), "r"(src_bytes));
}

__device__ __forceinline__ void mma_bf16(float c[4],
                                         uint32_t a0, uint32_t a1, uint32_t a2, uint32_t a3,
                                         uint32_t b0, uint32_t b1) {
    asm("mma.sync.aligned.m16n8k16.row.col.f32.bf16.bf16.f32 "
        "{%0,%1,%2,%3}, {%4,%5,%6,%7}, {%8,%9}, {%0,%1,%2,%3};"
        : "+f"(c[0]), "+f"(c[1]), "+f"(c[2]), "+f"(c[3])
        : "r"(a0), "r"(a1), "r"(a2), "r"(a3), "r"(b0), "r"(b1));
}

__global__ void __launch_bounds__(256, 2)
gemm_tc_kernel(int a_sel, int Kp, int wt_off,
               const float* __restrict__ Af32,
               const float* __restrict__ bias,
               float* C_ext, int write_split,
               int M, int do_relu) {
    extern __shared__ uint32_t ds[];
    uint32_t sb = (uint32_t)__cvta_generic_to_shared(ds);

    const uint32_t* Ah = (a_sel == 1) ? g_zh : g_ah;
    const uint32_t* Al = (a_sel == 1) ? g_zl : g_al;
    const uint32_t* WH = g_wbh + wt_off;
    const uint32_t* WL = g_wbl + wt_off;
    float* C = C_ext ? C_ext : g_h;

    int tid  = threadIdx.x;
    int wid  = tid >> 5;
    int lane = tid & 31;
    int wm   = wid & 3;
    int wn   = wid >> 2;
    int group = lane >> 2;
    int tig   = lane & 3;

    int row0 = blockIdx.y * GBM;
    int col0 = blockIdx.x * GBN;

    float acc[2][4][4];
#pragma unroll
    for (int mi = 0; mi < 2; mi++)
#pragma unroll
        for (int ni = 0; ni < 4; ni++)
#pragma unroll
            for (int q = 0; q < 4; q++) acc[mi][ni][q] = 0.0f;

    int nch = Kp / KPT;

    auto issueB = [&](int c, uint32_t base, uint32_t bh, uint32_t bl) {
        int k0p = c * KPT;
        int k2 = tid >> 4;             // 0..15
        int n4 = (tid & 15) * 4;
        cp_async16(base + (bh + k2 * BSTR + n4) * 4,
                   WH + (size_t)(k0p + k2) * M + col0 + n4, 16);
        cp_async16(base + (bl + k2 * BSTR + n4) * 4,
                   WL + (size_t)(k0p + k2) * M + col0 + n4, 16);
    };

    // ---- compute from stage (pointer bases) ----
    auto compute = [&](const uint32_t* AsH, const uint32_t* AsL,
                       const uint32_t* BsH, const uint32_t* BsL) {
#pragma unroll
        for (int ks = 0; ks < 2; ks++) {
            int kb = ks * 8;
            uint32_t ahi[2][4], alo[2][4];
            uint32_t bhi[4][2], blo[4][2];
#pragma unroll
            for (int mi = 0; mi < 2; mi++) {
                int m = wm * 32 + mi * 16 + group;
                ahi[mi][0] = AsH[(m    ) * ASTR + kb + tig];
                ahi[mi][1] = AsH[(m + 8) * ASTR + kb + tig];
                ahi[mi][2] = AsH[(m    ) * ASTR + kb + tig + 4];
                ahi[mi][3] = AsH[(m + 8) * ASTR + kb + tig + 4];
                alo[mi][0] = AsL[(m    ) * ASTR + kb + tig];
                alo[mi][1] = AsL[(m + 8) * ASTR + kb + tig];
                alo[mi][2] = AsL[(m    ) * ASTR + kb + tig + 4];
                alo[mi][3] = AsL[(m + 8) * ASTR + kb + tig + 4];
            }
#pragma unroll
            for (int ni = 0; ni < 4; ni++) {
                int n = wn * 32 + ni * 8 + group;
                bhi[ni][0] = BsH[(kb + tig    ) * BSTR + n];
                bhi[ni][1] = BsH[(kb + tig + 4) * BSTR + n];
                blo[ni][0] = BsL[(kb + tig    ) * BSTR + n];
                blo[ni][1] = BsL[(kb + tig + 4) * BSTR + n];
            }
#pragma unroll
            for (int ni = 0; ni < 4; ni++)
#pragma unroll
                for (int mi = 0; mi < 2; mi++)
                    mma_bf16(acc[mi][ni], ahi[mi][0], ahi[mi][1], ahi[mi][2], ahi[mi][3],
                             bhi[ni][0], bhi[ni][1]);
#pragma unroll
            for (int ni = 0; ni < 4; ni++)
#pragma unroll
                for (int mi = 0; mi < 2; mi++)
                    mma_bf16(acc[mi][ni], ahi[mi][0], ahi[mi][1], ahi[mi][2], ahi[mi][3],
                             blo[ni][0], blo[ni][1]);
#pragma unroll
            for (int ni = 0; ni < 4; ni++)
#pragma unroll
                for (int mi = 0; mi < 2; mi++)
                    mma_bf16(acc[mi][ni], alo[mi][0], alo[mi][1], alo[mi][2], alo[mi][3],
                             bhi[ni][0], bhi[ni][1]);
        }
    };

    if (a_sel != 2) {
        // ---------- 3-stage ring, pre-split A ----------
        auto issueLoads = [&](int c, int buf) {
            int k0p = c * KPT;
            uint32_t base = sb + (uint32_t)buf * SSZ * 4;
#pragma unroll
            for (int q = 0; q < 2; q++) {
                int f4 = tid * 2 + q;
                int r  = f4 >> 2;
                int c4 = (f4 & 3) * 4;
                int gr = row0 + r;
                int ok = (gr < NN) ? 16 : 0;
                int grc = (gr < NN) ? gr : (NN - 1);
                cp_async16(base + (r * ASTR + c4) * 4,
                           Ah + (size_t)grc * Kp + k0p + c4, ok);
                cp_async16(base + (AOFF_L + r * ASTR + c4) * 4,
                           Al + (size_t)grc * Kp + k0p + c4, ok);
            }
            issueB(c, base, BOFF_H, BOFF_L);
            asm volatile("cp.async.commit_group;");
        };

        issueLoads(0, 0);
        if (nch > 1) issueLoads(1, 1);
        int buf = 0;
        for (int c = 0; c < nch; c++) {
            if (c + 2 < nch) {
                int nb = (buf + 2) % 3;
                issueLoads(c + 2, nb);
                asm volatile("cp.async.wait_group 2;");
            } else if (c + 1 < nch) {
                asm volatile("cp.async.wait_group 1;");
            } else {
                asm volatile("cp.async.wait_group 0;");
            }
            __syncthreads();
            const uint32_t* st = ds + buf * SSZ;
            compute(st, st + AOFF_L, st + BOFF_H, st + BOFF_L);
            __syncthreads();
            buf = (buf + 1) % 3;
        }
    } else {
        // ---------- 2-stage, f32 A with fused split ----------
        int Kf = Kp * 2;     // f32 K (=256)
        auto issueLoads2 = [&](int c, int buf) {
            int k0f = c * KPT * 2;
            uint32_t base = sb + (uint32_t)buf * S2SZ * 4;
#pragma unroll
            for (int q = 0; q < 4; q++) {
                int f4 = tid + q * 256;       // 0..1023
                int r  = f4 >> 3;
                int c4 = (f4 & 7) * 4;
                int gr = row0 + r;
                int ok = (gr < NN) ? 16 : 0;
                int grc = (gr < NN) ? gr : (NN - 1);
                cp_async16(base + (r * 32 + c4) * 4,
                           Af32 + (size_t)grc * Kf + k0f + c4, ok);
            }
            issueB(c, base, M2_BH, M2_BL);
            asm volatile("cp.async.commit_group;");
        };

        auto convert2 = [&](int buf) {
            const float* AF = reinterpret_cast<const float*>(ds + buf * S2SZ);
            uint32_t* AsH = ds + buf * S2SZ + M2_AH;
            uint32_t* AsL = ds + buf * S2SZ + M2_AL;
#pragma unroll
            for (int q = 0; q < 4; q++) {
                int f4 = tid + q * 256;
                int r  = f4 >> 3;
                int ci = f4 & 7;
                float4 v = *reinterpret_cast<const float4*>(AF + r * 32 + ci * 4);
                uint32_t h0, l0, h1, l1;
                splitbf2(v.x, v.y, h0, l0);
                splitbf2(v.z, v.w, h1, l1);
                *reinterpret_cast<uint2*>(&AsH[r * ASTR + ci * 2]) = make_uint2(h0, h1);
                *reinterpret_cast<uint2*>(&AsL[r * ASTR + ci * 2]) = make_uint2(l0, l1);
            }
        };

        issueLoads2(0, 0);
        for (int c = 0; c < nch; c++) {
            int buf = c & 1;
            if (c + 1 < nch) {
                issueLoads2(c + 1, buf ^ 1);
                asm volatile("cp.async.wait_group 1;");
            } else {
                asm volatile("cp.async.wait_group 0;");
            }
            __syncthreads();
            convert2(buf);
            __syncthreads();
            const uint32_t* st = ds + buf * S2SZ;
            compute(st + M2_AH, st + M2_AL, st + M2_BH, st + M2_BL);
            __syncthreads();
        }
    }

    // ---- epilogue ----
#pragma unroll
    for (int mi = 0; mi < 2; mi++) {
#pragma unroll
        for (int ni = 0; ni < 4; ni++) {
            int colb = col0 + wn * 32 + ni * 8 + tig * 2;
            float b0 = 0.f, b1 = 0.f;
            if (bias) { b0 = bias[colb]; b1 = bias[colb + 1]; }
#pragma unroll
            for (int half = 0; half < 2; half++) {
                int r = row0 + wm * 32 + mi * 16 + group + half * 8;
                if (r >= NN) continue;
                float v0 = acc[mi][ni][half * 2 + 0] + b0;
                float v1 = acc[mi][ni][half * 2 + 1] + b1;
                if (do_relu) { v0 = fmaxf(v0, 0.f); v1 = fmaxf(v1, 0.f); }
                if (write_split) {
                    uint32_t h, l;
                    splitbf2(v0, v1, h, l);
                    size_t o = (size_t)r * (M >> 1) + (colb >> 1);
                    g_ah[o] = h;
                    g_al[o] = l;
                } else {
                    *reinterpret_cast<float2*>(C + (size_t)r * M + colb) = make_float2(v0, v1);
                }
            }
        }
    }
}

// ---------------- orchestration ----------------------------------------------
static inline void run_gemm(int a_sel, int Kp, int wt_off, const float* Af32,
                            const float* bias, float* C_ext, int write_split,
                            int M, int relu) {
    dim3 grid(M / GBN, (NN + GBM - 1) / GBM);
    size_t smem = (a_sel == 2) ? GEMM_SMEM_2 : GEMM_SMEM_01;
    gemm_tc_kernel<<<grid, 256, smem>>>(a_sel, Kp, wt_off, Af32, bias, C_ext,
                                        write_split, M, relu);
}

extern "C" void kernel_launch(void* const* d_in, const int* in_sizes, int n_in,
                              void* d_out, int out_size) {
    const float* x   = (const float*)d_in[0];
    const void*  ei  = d_in[1];
    const float* W1  = (const float*)d_in[2];
    const float* b1  = (const float*)d_in[3];
    const float* W2  = (const float*)d_in[4];
    const float* b2  = (const float*)d_in[5];
    const float* W3  = (const float*)d_in[6];
    const float* b3  = (const float*)d_in[7];
    const float* Wd1 = (const float*)d_in[8];
    const float* bd1 = (const float*)d_in[9];
    const float* Wd2 = (const float*)d_in[10];
    const float* bd2 = (const float*)d_in[11];

    float* z    = (float*)d_out;                     // [N, 64]
    float* xhat = (float*)d_out + (size_t)NN * DE;   // [N, 256]

    cudaFuncSetAttribute(gemm_tc_kernel,
                         cudaFuncAttributeMaxDynamicSharedMemorySize, GEMM_SMEM_MAX);

    // ---- graph preprocessing + weight pre-split -------------------------
    detect_kernel<<<1, 32>>>((const int*)ei);
    zero_cnt_kernel<<<(NN + 255) / 256, 256>>>();
    convert_kernel<<<(2 * EE + 255) / 256, 256>>>(ei);
    scan1_kernel<<<NB, 1024>>>();
    scan2_kernel<<<1, 32>>>();
    scan3_kernel<<<(NN + 255) / 256, 256>>>();
    fill_csr_kernel<<<(EE + 255) / 256, 256>>>();
    wsplit_kernel<<<(WPACKS + 255) / 256, 256>>>(W1, W2, W3, Wd1, Wd2);

    int aggBlocks = (NN + 7) / 8;

    // ---- layer 1: h1 = relu(gcn(x, W1, b1)) -----------------------------
    run_gemm(2, 128, OFF_W1, x, nullptr, nullptr, 0, DH, 0);   // fused x split
    agg_d128_kernel<<<aggBlocks, 256>>>(b1);                   // -> g_ah/g_al

    // ---- layer 2: h2 = relu(gcn(h1, W2, b2)) ----------------------------
    run_gemm(0, 64, OFF_W2, nullptr, nullptr, nullptr, 0, DH, 0);
    agg_d128_kernel<<<aggBlocks, 256>>>(b2);

    // ---- layer 3: z = gcn(h2, W3, b3) -----------------------------------
    run_gemm(0, 64, OFF_W3, nullptr, nullptr, nullptr, 0, DE, 0);
    agg_d64_kernel<<<aggBlocks, 256>>>(b3, z);                 // z f32 + g_zh/zl

    // ---- decoder: x_hat = relu(z@Wd1+bd1)@Wd2 + bd2 ---------------------
    run_gemm(1, 32, OFF_WD1, nullptr, bd1, nullptr, 1, DH, 1); // split -> g_ah/al
    run_gemm(0, 64, OFF_WD2, nullptr, bd2, xhat, 0, DIN, 0);
}